// round 16
// baseline (speedup 1.0000x reference)
#include <cuda_runtime.h>
#include <cuda_fp16.h>
#include <mma.h>
using namespace nvcuda;

// Problem constants (fixed by the dataset)
#define F_DIM   128
#define MAXN    10240
#define MAXE    655360
#define ATT_SCALE 0.17677669529663687f   // 1/sqrt(32)
#define LN_EPS  1e-5f
#define MBLK 64
#define NBLK 64

// ---------------- scratch (device globals; no allocation allowed) -------------
__device__ float  g_Xpad[MAXN * F_DIM];  // tf32-rounded, zero-padded X
__device__ __half g_Qh[MAXN * F_DIM];    // fp16 Q, pre-scaled by ATT_SCALE
__device__ __half g_KV[MAXN * 256];      // per node: 128 K halfs then 128 V halfs
__device__ float  g_R[MAXN * F_DIM];
__device__ int    g_counts[MAXN];
__device__ int    g_offs[MAXN + 1];
__device__ int    g_rank[MAXE];          // per-edge rank within its dst segment
__device__ int    g_srcsorted[MAXE];

// ---------------- K0: copy X -> tf32-rounded zero-padded buffer ----------------
__global__ void k_copyX(const float* __restrict__ X, int N, int padN) {
    const int i = blockIdx.x * 256 + threadIdx.x;
    const int node = i >> 7;
    if (node < padN)
        g_Xpad[i] = (node < N) ? wmma::__float_to_tf32(X[i]) : 0.f;
}

// ---------------- K1: tensor-core QKVR projections + dst histogram+rank --------
// grid = (ceil(N/64), 8). A fragments preloaded in TWO batches of 8 (MLP=8,
// moderate register pressure). Batch 0 overlaps the B smem staging + barrier;
// batch 1 overlaps the first 8 mma steps.
__global__ __launch_bounds__(128) void k_qkv_tc(
    const float* __restrict__ WQ, const float* __restrict__ WK,
    const float* __restrict__ WV, const float* __restrict__ WR,
    const float* __restrict__ br,
    const int* __restrict__ dst, int N, int E, int epb)
{
    __shared__ float Bs[128][68];        // [k][n], tf32-rounded; 34.8 KB

    const int tid  = threadIdx.x;
    const int w    = tid >> 5;
    const int lane = tid & 31;

    const int ncol0 = blockIdx.y * NBLK;
    const int mat   = ncol0 >> 7;        // 0=Q 1=K 2=V 3=R
    const int c0    = ncol0 & 127;
    const float* __restrict__ W =
        (mat == 0) ? WQ : (mat == 1) ? WK : (mat == 2) ? WV : WR;

    const int m0 = blockIdx.x * MBLK + w * 16;
    const float* Arow = g_Xpad + m0 * F_DIM;

    // batch 0: preload A fragments k=0..7 (32 LDGs back-to-back per lane)
    wmma::fragment<wmma::matrix_a, 16, 16, 8, wmma::precision::tf32,
                   wmma::row_major> a0[8];
    #pragma unroll
    for (int k = 0; k < 8; ++k)
        wmma::load_matrix_sync(a0[k], Arow + k * 8, F_DIM);

    // stage W tile [128 x 64] into smem (overlaps batch-0 latency)
    for (int i = tid; i < 128 * 64; i += 128) {
        const int f = i >> 6, c = i & 63;
        Bs[f][c] = wmma::__float_to_tf32(__ldg(&W[f * F_DIM + c0 + c]));
    }
    __syncthreads();

    wmma::fragment<wmma::accumulator, 16, 16, 8, float> acc[4];
    #pragma unroll
    for (int j = 0; j < 4; ++j) wmma::fill_fragment(acc[j], 0.f);

    // batch 1: issue A fragment loads k=8..15, then immediately start mma on
    // batch 0 — batch-1 latency hides under the first 32 mmas.
    wmma::fragment<wmma::matrix_a, 16, 16, 8, wmma::precision::tf32,
                   wmma::row_major> a1[8];
    #pragma unroll
    for (int k = 0; k < 8; ++k)
        wmma::load_matrix_sync(a1[k], Arow + (8 + k) * 8, F_DIM);

    #pragma unroll
    for (int k = 0; k < 8; ++k) {
        #pragma unroll
        for (int j = 0; j < 4; ++j) {
            wmma::fragment<wmma::matrix_b, 16, 16, 8, wmma::precision::tf32,
                           wmma::row_major> b;
            wmma::load_matrix_sync(b, &Bs[k * 8][j * 16], 68);
            wmma::mma_sync(acc[j], a0[k], b, acc[j]);
        }
    }
    #pragma unroll
    for (int k = 0; k < 8; ++k) {
        #pragma unroll
        for (int j = 0; j < 4; ++j) {
            wmma::fragment<wmma::matrix_b, 16, 16, 8, wmma::precision::tf32,
                           wmma::row_major> b;
            wmma::load_matrix_sync(b, &Bs[(8 + k) * 8][j * 16], 68);
            wmma::mma_sync(acc[j], a1[k], b, acc[j]);
        }
    }

    // epilogue: stage through smem (alias Bs after barrier), typed stores
    __syncthreads();
    float* Cw = reinterpret_cast<float*>(Bs) + w * (16 * 68);
    #pragma unroll
    for (int j = 0; j < 4; ++j)
        wmma::store_matrix_sync(Cw + j * 16, acc[j], 68, wmma::mem_row_major);
    __syncwarp();

    for (int r = 0; r < 16; ++r) {
        const int node = m0 + r;
        if (node >= N) break;
        #pragma unroll
        for (int c = lane; c < 64; c += 32) {
            const float v = Cw[r * 68 + c];
            const int col = c0 + c;
            if      (mat == 0) g_Qh[node * F_DIM + col] =
                                   __float2half_rn(v * ATT_SCALE);
            else if (mat == 1) g_KV[node * 256 + col]       = __float2half_rn(v);
            else if (mat == 2) g_KV[node * 256 + 128 + col] = __float2half_rn(v);
            else               g_R[node * F_DIM + col] = v + __ldg(&br[col]);
        }
    }

    // fused dst histogram + rank capture
    const int bid = blockIdx.y * gridDim.x + blockIdx.x;
    const int e0 = bid * epb;
    const int e1 = min(e0 + epb, E);
    for (int e = e0 + tid; e < e1; e += 128)
        g_rank[e] = atomicAdd(&g_counts[__ldg(&dst[e])], 1);
}

// ---------------- K2: exclusive scan (warp-shuffle, 2 barriers) ----------------
__global__ __launch_bounds__(1024) void k_scan(int N, int E) {
    __shared__ int wsum[32];
    const int t = threadIdx.x;
    const int lane = t & 31, w = t >> 5;
    const int base = t * 10;

    int loc[10];
    int s = 0;
    #pragma unroll
    for (int i = 0; i < 10; ++i) {
        const int idx = base + i;
        loc[i] = (idx < N) ? g_counts[idx] : 0;
        s += loc[i];
    }
    int inc = s;
    #pragma unroll
    for (int o = 1; o < 32; o <<= 1) {
        int v = __shfl_up_sync(0xffffffffu, inc, o);
        if (lane >= o) inc += v;
    }
    if (lane == 31) wsum[w] = inc;
    __syncthreads();
    if (w == 0) {
        int v = wsum[lane];
        #pragma unroll
        for (int o = 1; o < 32; o <<= 1) {
            int u = __shfl_up_sync(0xffffffffu, v, o);
            if (lane >= o) v += u;
        }
        wsum[lane] = v;
    }
    __syncthreads();
    int run = ((w == 0) ? 0 : wsum[w - 1]) + (inc - s);
    #pragma unroll
    for (int i = 0; i < 10; ++i) {
        const int idx = base + i;
        if (idx < N) g_offs[idx] = run, run += loc[i];
    }
    if (t == 0) g_offs[N] = E;
}

// ---------------- K3: scatter edges into CSR order (NO atomics) ----------------
__global__ __launch_bounds__(256) void k_scatter(
    const int* __restrict__ src, const int* __restrict__ dst, int E)
{
    const int base = (blockIdx.x * blockDim.x + threadIdx.x) * 4;
    if (base + 3 < E) {
        const int4 d = *reinterpret_cast<const int4*>(dst + base);
        const int4 s = *reinterpret_cast<const int4*>(src + base);
        const int4 r = *reinterpret_cast<const int4*>(g_rank + base);
        g_srcsorted[g_offs[d.x] + r.x] = s.x;
        g_srcsorted[g_offs[d.y] + r.y] = s.y;
        g_srcsorted[g_offs[d.z] + r.z] = s.z;
        g_srcsorted[g_offs[d.w] + r.w] = s.w;
    } else {
        for (int e = base; e < E; ++e)
            g_srcsorted[g_offs[dst[e]] + g_rank[e]] = src[e];
    }
}

// ---------------- K4: fused attention + residual + LayerNorm -------------------
// One warp per node, HALF-WARP PER EDGE (R14 version, measured good).
__global__ __launch_bounds__(256) void k_attn(
    const float* __restrict__ gamma, const float* __restrict__ beta,
    float* __restrict__ out, int N)
{
    const unsigned FULL = 0xffffffffu;
    const int warp = (blockIdx.x * blockDim.x + threadIdx.x) >> 5;
    if (warp >= N) return;
    const int lane = threadIdx.x & 31;
    const int g = lane & 15;
    const int half_id = lane >> 4;

    const uint4 qv = ((const uint4*)g_Qh)[warp * 16 + g];
    const __half2* qh = (const __half2*)&qv;

    const uint4* __restrict__ KV4 = (const uint4*)g_KV;  // 32 uint4/node: K then V

    float acc[8] = {0.f, 0.f, 0.f, 0.f, 0.f, 0.f, 0.f, 0.f};
    float ssum = 0.f;

    const int beg = g_offs[warp];
    const int end = g_offs[warp + 1];

    for (int base = beg; base < end; base += 32) {
        const int idx = base + lane;
        const int mysrc = (idx < end) ? g_srcsorted[idx] : 0;
        const int cnt = min(32, end - base);
        #pragma unroll 2
        for (int j = 0; j < cnt; j += 2) {
            const int el = j + half_id;
            const int src = __shfl_sync(FULL, mysrc, el & 31);
            const uint4 ku = KV4[src * 32 + g];
            const uint4 vu = KV4[src * 32 + 16 + g];
            const __half2* kh = (const __half2*)&ku;
            __half2 d0 = __hmul2(qh[0], kh[0]);
            __half2 d1 = __hmul2(qh[1], kh[1]);
            d0 = __hfma2(qh[2], kh[2], d0);
            d1 = __hfma2(qh[3], kh[3], d1);
            const float2 pf = __half22float2(__hadd2(d0, d1));
            float p = pf.x + pf.y;
            p += __shfl_xor_sync(FULL, p, 1);
            p += __shfl_xor_sync(FULL, p, 2);
            const float w = (el < cnt) ? __expf(p) : 0.f;
            ssum += w;
            const __half2* vh = (const __half2*)&vu;
            #pragma unroll
            for (int i = 0; i < 4; ++i) {
                const float2 vf = __half22float2(vh[i]);
                acc[2 * i]     = fmaf(w, vf.x, acc[2 * i]);
                acc[2 * i + 1] = fmaf(w, vf.y, acc[2 * i + 1]);
            }
        }
    }

    ssum += __shfl_xor_sync(FULL, ssum, 16);
    #pragma unroll
    for (int i = 0; i < 8; ++i) acc[i] += __shfl_xor_sync(FULL, acc[i], 16);

    const float inv = 1.f / (ssum + 1e-12f);
    const int vecIdx = warp * 32 + g * 2 + half_id;
    const float4 r = ((const float4*)g_R)[vecIdx];
    const float* ah = acc + 4 * half_id;
    float4 h;
    h.x = fmaf(ah[0], inv, r.x);
    h.y = fmaf(ah[1], inv, r.y);
    h.z = fmaf(ah[2], inv, r.z);
    h.w = fmaf(ah[3], inv, r.w);

    float s1 = h.x + h.y + h.z + h.w;
    float s2 = h.x * h.x + h.y * h.y + h.z * h.z + h.w * h.w;
    #pragma unroll
    for (int o = 16; o; o >>= 1) {
        s1 += __shfl_xor_sync(FULL, s1, o);
        s2 += __shfl_xor_sync(FULL, s2, o);
    }
    const float mu  = s1 * (1.f / 128.f);
    const float var = s2 * (1.f / 128.f) - mu * mu;
    const float rs  = rsqrtf(var + LN_EPS);

    const float4 gg = ((const float4*)gamma)[g * 2 + half_id];
    const float4 bb = ((const float4*)beta)[g * 2 + half_id];
    float4 o4;
    o4.x = fmaf(gg.x * (h.x - mu), rs, bb.x);
    o4.y = fmaf(gg.y * (h.y - mu), rs, bb.y);
    o4.z = fmaf(gg.z * (h.z - mu), rs, bb.z);
    o4.w = fmaf(gg.w * (h.w - mu), rs, bb.w);
    ((float4*)out)[vecIdx] = o4;
}

// ---------------- launch -------------------------------------------------------
extern "C" void kernel_launch(void* const* d_in, const int* in_sizes, int n_in,
                              void* d_out, int out_size)
{
    const float* nodes = (const float*)d_in[0];
    const float* WQ    = (const float*)d_in[1];
    const float* WK    = (const float*)d_in[2];
    const float* WV    = (const float*)d_in[3];
    const float* WR    = (const float*)d_in[4];
    const float* br    = (const float*)d_in[5];
    const float* gamma = (const float*)d_in[6];
    const float* beta  = (const float*)d_in[7];
    const int*   ei    = (const int*)d_in[8];

    const int N = in_sizes[0] / F_DIM;
    const int E = in_sizes[8] / 2;
    const int* src = ei;
    const int* dst = ei + E;

    const int mblocks = (N + MBLK - 1) / MBLK;
    const int padN    = mblocks * MBLK;
    const int nblk    = mblocks * 8;
    const int epb     = (E + nblk - 1) / nblk;

    void* cnt_ptr = nullptr;
    cudaGetSymbolAddress(&cnt_ptr, g_counts);
    cudaMemsetAsync(cnt_ptr, 0, N * sizeof(int));

    k_copyX<<<(padN * F_DIM + 255) / 256, 256>>>(nodes, N, padN);
    dim3 grid_tc(mblocks, 8);
    k_qkv_tc<<<grid_tc, 128>>>(WQ, WK, WV, WR, br, dst, N, E, epb);
    k_scan<<<1, 1024>>>(N, E);
    k_scatter<<<((E + 3) / 4 + 255) / 256, 256>>>(src, dst, E);
    k_attn<<<(N + 7) / 8, 256>>>(gamma, beta, (float*)d_out, N);
}

// round 17
// speedup vs baseline: 1.2661x; 1.2661x over previous
#include <cuda_runtime.h>
#include <cuda_fp16.h>
#include <mma.h>
using namespace nvcuda;

// Problem constants (fixed by the dataset)
#define F_DIM   128
#define MAXN    10240
#define MAXE    655360
#define ATT_SCALE 0.17677669529663687f   // 1/sqrt(32)
#define LN_EPS  1e-5f
#define MBLK 64
#define NBLK 64

// ---------------- scratch (device globals; no allocation allowed) -------------
__device__ __half g_Xh[MAXN * F_DIM];    // fp16 X, zero-padded
__device__ __half g_Qh[MAXN * F_DIM];    // fp16 Q, pre-scaled by ATT_SCALE
__device__ __half g_KV[MAXN * 256];      // per node: 128 K halfs then 128 V halfs
__device__ float  g_R[MAXN * F_DIM];
__device__ int    g_counts[MAXN];
__device__ int    g_offs[MAXN + 1];
__device__ int    g_rank[MAXE];          // per-edge rank within its dst segment
__device__ int    g_srcsorted[MAXE];

// ---------------- K0: copy X -> fp16 zero-padded buffer ------------------------
__global__ void k_copyX(const float* __restrict__ X, int N, int padN) {
    const int i4 = blockIdx.x * 256 + threadIdx.x;   // one float4 -> one half4
    const int node = i4 >> 5;                        // 32 float4 per node row
    if (node >= padN) return;
    uint2 o = make_uint2(0u, 0u);
    if (node < N) {
        const float4 v = *reinterpret_cast<const float4*>(X + i4 * 4);
        __half2 lo = __floats2half2_rn(v.x, v.y);
        __half2 hi = __floats2half2_rn(v.z, v.w);
        o.x = *reinterpret_cast<unsigned*>(&lo);
        o.y = *reinterpret_cast<unsigned*>(&hi);
    }
    reinterpret_cast<uint2*>(g_Xh)[i4] = o;
}

// ---------------- K1: fp16 tensor-core QKVR projections + histogram+rank -------
// grid = (ceil(N/64), 8). blockIdx.y picks a 64-col slice of the 512 output
// columns (4 matrices x 128). fp16 HMMA 16x16x16: 8 k-steps x 4 n-slices per
// warp. B tile fp16 in smem (18 KB -> high occupancy).
__global__ __launch_bounds__(128) void k_qkv_tc(
    const float* __restrict__ WQ, const float* __restrict__ WK,
    const float* __restrict__ WV, const float* __restrict__ WR,
    const float* __restrict__ br,
    const int* __restrict__ dst, int N, int E, int epb)
{
    __shared__ __half Bs[128][72];       // [k][n] fp16; 18 KB

    const int tid  = threadIdx.x;
    const int w    = tid >> 5;
    const int lane = tid & 31;

    const int ncol0 = blockIdx.y * NBLK;
    const int mat   = ncol0 >> 7;        // 0=Q 1=K 2=V 3=R
    const int c0    = ncol0 & 127;
    const float* __restrict__ W =
        (mat == 0) ? WQ : (mat == 1) ? WK : (mat == 2) ? WV : WR;

    // stage W tile [128 x 64] into smem as fp16
    for (int i = tid; i < 128 * 64; i += 128) {
        const int f = i >> 6, c = i & 63;
        Bs[f][c] = __float2half_rn(__ldg(&W[f * F_DIM + c0 + c]));
    }
    __syncthreads();

    const int m0 = blockIdx.x * MBLK + w * 16;
    const __half* Arow = g_Xh + m0 * F_DIM;

    wmma::fragment<wmma::accumulator, 16, 16, 16, float> acc[4];
    #pragma unroll
    for (int j = 0; j < 4; ++j) wmma::fill_fragment(acc[j], 0.f);

    #pragma unroll
    for (int k = 0; k < 8; ++k) {
        wmma::fragment<wmma::matrix_a, 16, 16, 16, __half, wmma::row_major> a;
        wmma::load_matrix_sync(a, Arow + k * 16, F_DIM);
        #pragma unroll
        for (int j = 0; j < 4; ++j) {
            wmma::fragment<wmma::matrix_b, 16, 16, 16, __half, wmma::row_major> b;
            wmma::load_matrix_sync(b, &Bs[k * 16][j * 16], 72);
            wmma::mma_sync(acc[j], a, b, acc[j]);
        }
    }

    // epilogue: stage fp32 C through smem (alias Bs after barrier)
    __syncthreads();
    float* Cw = reinterpret_cast<float*>(Bs) + w * (16 * 68);
    #pragma unroll
    for (int j = 0; j < 4; ++j)
        wmma::store_matrix_sync(Cw + j * 16, acc[j], 68, wmma::mem_row_major);
    __syncwarp();

    for (int r = 0; r < 16; ++r) {
        const int node = m0 + r;
        if (node >= N) break;
        #pragma unroll
        for (int c = lane; c < 64; c += 32) {
            const float v = Cw[r * 68 + c];
            const int col = c0 + c;
            if      (mat == 0) g_Qh[node * F_DIM + col] =
                                   __float2half_rn(v * ATT_SCALE);
            else if (mat == 1) g_KV[node * 256 + col]       = __float2half_rn(v);
            else if (mat == 2) g_KV[node * 256 + 128 + col] = __float2half_rn(v);
            else               g_R[node * F_DIM + col] = v + __ldg(&br[col]);
        }
    }

    // fused dst histogram + rank capture
    const int bid = blockIdx.y * gridDim.x + blockIdx.x;
    const int e0 = bid * epb;
    const int e1 = min(e0 + epb, E);
    for (int e = e0 + tid; e < e1; e += 128)
        g_rank[e] = atomicAdd(&g_counts[__ldg(&dst[e])], 1);
}

// ---------------- K2: exclusive scan (warp-shuffle, 2 barriers) ----------------
__global__ __launch_bounds__(1024) void k_scan(int N, int E) {
    __shared__ int wsum[32];
    const int t = threadIdx.x;
    const int lane = t & 31, w = t >> 5;
    const int base = t * 10;

    int loc[10];
    int s = 0;
    #pragma unroll
    for (int i = 0; i < 10; ++i) {
        const int idx = base + i;
        loc[i] = (idx < N) ? g_counts[idx] : 0;
        s += loc[i];
    }
    int inc = s;
    #pragma unroll
    for (int o = 1; o < 32; o <<= 1) {
        int v = __shfl_up_sync(0xffffffffu, inc, o);
        if (lane >= o) inc += v;
    }
    if (lane == 31) wsum[w] = inc;
    __syncthreads();
    if (w == 0) {
        int v = wsum[lane];
        #pragma unroll
        for (int o = 1; o < 32; o <<= 1) {
            int u = __shfl_up_sync(0xffffffffu, v, o);
            if (lane >= o) v += u;
        }
        wsum[lane] = v;
    }
    __syncthreads();
    int run = ((w == 0) ? 0 : wsum[w - 1]) + (inc - s);
    #pragma unroll
    for (int i = 0; i < 10; ++i) {
        const int idx = base + i;
        if (idx < N) g_offs[idx] = run, run += loc[i];
    }
    if (t == 0) g_offs[N] = E;
}

// ---------------- K3: scatter edges into CSR order (NO atomics) ----------------
__global__ __launch_bounds__(256) void k_scatter(
    const int* __restrict__ src, const int* __restrict__ dst, int E)
{
    const int base = (blockIdx.x * blockDim.x + threadIdx.x) * 4;
    if (base + 3 < E) {
        const int4 d = *reinterpret_cast<const int4*>(dst + base);
        const int4 s = *reinterpret_cast<const int4*>(src + base);
        const int4 r = *reinterpret_cast<const int4*>(g_rank + base);
        g_srcsorted[g_offs[d.x] + r.x] = s.x;
        g_srcsorted[g_offs[d.y] + r.y] = s.y;
        g_srcsorted[g_offs[d.z] + r.z] = s.z;
        g_srcsorted[g_offs[d.w] + r.w] = s.w;
    } else {
        for (int e = base; e < E; ++e)
            g_srcsorted[g_offs[dst[e]] + g_rank[e]] = src[e];
    }
}

// ---------------- K4: fused attention + residual + LayerNorm -------------------
// One warp per node, HALF-WARP PER EDGE (R14 version, measured good).
__global__ __launch_bounds__(256) void k_attn(
    const float* __restrict__ gamma, const float* __restrict__ beta,
    float* __restrict__ out, int N)
{
    const unsigned FULL = 0xffffffffu;
    const int warp = (blockIdx.x * blockDim.x + threadIdx.x) >> 5;
    if (warp >= N) return;
    const int lane = threadIdx.x & 31;
    const int g = lane & 15;
    const int half_id = lane >> 4;

    const uint4 qv = ((const uint4*)g_Qh)[warp * 16 + g];
    const __half2* qh = (const __half2*)&qv;

    const uint4* __restrict__ KV4 = (const uint4*)g_KV;  // 32 uint4/node: K then V

    float acc[8] = {0.f, 0.f, 0.f, 0.f, 0.f, 0.f, 0.f, 0.f};
    float ssum = 0.f;

    const int beg = g_offs[warp];
    const int end = g_offs[warp + 1];

    for (int base = beg; base < end; base += 32) {
        const int idx = base + lane;
        const int mysrc = (idx < end) ? g_srcsorted[idx] : 0;
        const int cnt = min(32, end - base);
        #pragma unroll 2
        for (int j = 0; j < cnt; j += 2) {
            const int el = j + half_id;
            const int src = __shfl_sync(FULL, mysrc, el & 31);
            const uint4 ku = KV4[src * 32 + g];
            const uint4 vu = KV4[src * 32 + 16 + g];
            const __half2* kh = (const __half2*)&ku;
            __half2 d0 = __hmul2(qh[0], kh[0]);
            __half2 d1 = __hmul2(qh[1], kh[1]);
            d0 = __hfma2(qh[2], kh[2], d0);
            d1 = __hfma2(qh[3], kh[3], d1);
            const float2 pf = __half22float2(__hadd2(d0, d1));
            float p = pf.x + pf.y;
            p += __shfl_xor_sync(FULL, p, 1);
            p += __shfl_xor_sync(FULL, p, 2);
            const float w = (el < cnt) ? __expf(p) : 0.f;
            ssum += w;
            const __half2* vh = (const __half2*)&vu;
            #pragma unroll
            for (int i = 0; i < 4; ++i) {
                const float2 vf = __half22float2(vh[i]);
                acc[2 * i]     = fmaf(w, vf.x, acc[2 * i]);
                acc[2 * i + 1] = fmaf(w, vf.y, acc[2 * i + 1]);
            }
        }
    }

    ssum += __shfl_xor_sync(FULL, ssum, 16);
    #pragma unroll
    for (int i = 0; i < 8; ++i) acc[i] += __shfl_xor_sync(FULL, acc[i], 16);

    const float inv = 1.f / (ssum + 1e-12f);
    const int vecIdx = warp * 32 + g * 2 + half_id;
    const float4 r = ((const float4*)g_R)[vecIdx];
    const float* ah = acc + 4 * half_id;
    float4 h;
    h.x = fmaf(ah[0], inv, r.x);
    h.y = fmaf(ah[1], inv, r.y);
    h.z = fmaf(ah[2], inv, r.z);
    h.w = fmaf(ah[3], inv, r.w);

    float s1 = h.x + h.y + h.z + h.w;
    float s2 = h.x * h.x + h.y * h.y + h.z * h.z + h.w * h.w;
    #pragma unroll
    for (int o = 16; o; o >>= 1) {
        s1 += __shfl_xor_sync(FULL, s1, o);
        s2 += __shfl_xor_sync(FULL, s2, o);
    }
    const float mu  = s1 * (1.f / 128.f);
    const float var = s2 * (1.f / 128.f) - mu * mu;
    const float rs  = rsqrtf(var + LN_EPS);

    const float4 gg = ((const float4*)gamma)[g * 2 + half_id];
    const float4 bb = ((const float4*)beta)[g * 2 + half_id];
    float4 o4;
    o4.x = fmaf(gg.x * (h.x - mu), rs, bb.x);
    o4.y = fmaf(gg.y * (h.y - mu), rs, bb.y);
    o4.z = fmaf(gg.z * (h.z - mu), rs, bb.z);
    o4.w = fmaf(gg.w * (h.w - mu), rs, bb.w);
    ((float4*)out)[vecIdx] = o4;
}

// ---------------- launch -------------------------------------------------------
extern "C" void kernel_launch(void* const* d_in, const int* in_sizes, int n_in,
                              void* d_out, int out_size)
{
    const float* nodes = (const float*)d_in[0];
    const float* WQ    = (const float*)d_in[1];
    const float* WK    = (const float*)d_in[2];
    const float* WV    = (const float*)d_in[3];
    const float* WR    = (const float*)d_in[4];
    const float* br    = (const float*)d_in[5];
    const float* gamma = (const float*)d_in[6];
    const float* beta  = (const float*)d_in[7];
    const int*   ei    = (const int*)d_in[8];

    const int N = in_sizes[0] / F_DIM;
    const int E = in_sizes[8] / 2;
    const int* src = ei;
    const int* dst = ei + E;

    const int mblocks = (N + MBLK - 1) / MBLK;
    const int padN    = mblocks * MBLK;
    const int nblk    = mblocks * 8;
    const int epb     = (E + nblk - 1) / nblk;

    void* cnt_ptr = nullptr;
    cudaGetSymbolAddress(&cnt_ptr, g_counts);
    cudaMemsetAsync(cnt_ptr, 0, N * sizeof(int));

    k_copyX<<<(padN * 32 + 255) / 256, 256>>>(nodes, N, padN);
    dim3 grid_tc(mblocks, 8);
    k_qkv_tc<<<grid_tc, 128>>>(WQ, WK, WV, WR, br, dst, N, E, epb);
    k_scan<<<1, 1024>>>(N, E);
    k_scatter<<<((E + 3) / 4 + 255) / 256, 256>>>(src, dst, E);
    k_attn<<<(N + 7) / 8, 256>>>(gamma, beta, (float*)d_out, N);
}